// round 2
// baseline (speedup 1.0000x reference)
#include <cuda_runtime.h>
#include <cuda_bf16.h>
#include <cstdint>

// ------------------------------------------------------------------
// Problem constants
// ------------------------------------------------------------------
constexpr int N_ROWS = 8192;
constexpr int DIM    = 1024;
constexpr float SQRT_INV_TEMP = 2.23606797749978969f;   // sqrt(1/0.2)

constexpr int TM = 128;               // CTA tile rows
constexpr int TN = 128;               // CTA tile cols
constexpr int TK = 64;                // bf16 K elems per stage (128 B rows)
constexpr int STAGES  = 3;
constexpr int THREADS = 256;          // 8 warps, 2 (M) x 4 (N)
constexpr int NKC = DIM / TK;         // 16 K chunks

constexpr int A_BYTES   = TM * TK * 2;            // 16 KB
constexpr int B_BYTES   = TN * TK * 2;            // 16 KB
constexpr int STG_BYTES = A_BYTES + B_BYTES;      // 32 KB
constexpr int SMEM_BYTES = STAGES * STG_BYTES;    // 96 KB

constexpr int NTILE   = N_ROWS / TM;              // 64 -> grid 64*64
constexpr int NSTRIPE = N_ROWS / 32;              // 256 col stripes of 32

// ------------------------------------------------------------------
// Device scratch (static globals: allocation-free)
// ------------------------------------------------------------------
__device__ __nv_bfloat16 g_x[(size_t)N_ROWS * DIM];   // normalized * sqrt(5)
__device__ float g_ps[NSTRIPE * N_ROWS];              // partial sum exp(sim)
__device__ float g_pa[NSTRIPE * N_ROWS];              // partial sum lbl*sim
__device__ float g_pb[NSTRIPE * N_ROWS];              // partial sum lbl
__device__ float g_rowloss[N_ROWS];

// ------------------------------------------------------------------
// PTX helpers
// ------------------------------------------------------------------
__device__ __forceinline__ uint32_t smem_u32(const void* p) {
    uint32_t a;
    asm("{ .reg .u64 t; cvta.to.shared.u64 t, %1; cvt.u32.u64 %0, t; }" : "=r"(a) : "l"(p));
    return a;
}

__device__ __forceinline__ void cp_async16(uint32_t dst, const void* src) {
    asm volatile("{ .reg .u64 g; cvta.to.global.u64 g, %1; "
                 "cp.async.cg.shared.global [%0], [g], 16; }"
                 :: "r"(dst), "l"(src) : "memory");
}
#define CP_COMMIT() asm volatile("cp.async.commit_group;" ::: "memory")
#define CP_WAIT(N)  asm volatile("cp.async.wait_group %0;" :: "n"(N) : "memory")

#define LDSM_X4(R0, R1, R2, R3, ADDR) \
    asm volatile("ldmatrix.sync.aligned.m8n8.x4.shared.b16 {%0,%1,%2,%3}, [%4];" \
                 : "=r"(R0), "=r"(R1), "=r"(R2), "=r"(R3) : "r"(ADDR))

__device__ __forceinline__ void mma_bf16(float* d, const uint32_t* a, const uint32_t* b) {
    asm volatile(
        "mma.sync.aligned.m16n8k16.row.col.f32.bf16.bf16.f32 "
        "{%0,%1,%2,%3}, {%4,%5,%6,%7}, {%8,%9}, {%0,%1,%2,%3};"
        : "+f"(d[0]), "+f"(d[1]), "+f"(d[2]), "+f"(d[3])
        : "r"(a[0]), "r"(a[1]), "r"(a[2]), "r"(a[3]), "r"(b[0]), "r"(b[1]));
}

// ------------------------------------------------------------------
// Kernel 1: row-normalize, fold sqrt(1/T), cast to bf16
// ------------------------------------------------------------------
__global__ __launch_bounds__(256) void coref_norm_kernel(const float* __restrict__ e) {
    const int row = blockIdx.x, t = threadIdx.x;
    const float* r = e + (size_t)row * DIM;
    float x0 = r[t], x1 = r[t + 256], x2 = r[t + 512], x3 = r[t + 768];
    float ss = x0 * x0 + x1 * x1 + x2 * x2 + x3 * x3;
    #pragma unroll
    for (int o = 16; o > 0; o >>= 1) ss += __shfl_xor_sync(0xffffffffu, ss, o);
    __shared__ float ws[8];
    if ((t & 31) == 0) ws[t >> 5] = ss;
    __syncthreads();
    float tot = ws[0] + ws[1] + ws[2] + ws[3] + ws[4] + ws[5] + ws[6] + ws[7];
    float scale = SQRT_INV_TEMP / fmaxf(sqrtf(tot), 1e-8f);
    __nv_bfloat16* op = g_x + (size_t)row * DIM;
    op[t]       = __float2bfloat16(x0 * scale);
    op[t + 256] = __float2bfloat16(x1 * scale);
    op[t + 512] = __float2bfloat16(x2 * scale);
    op[t + 768] = __float2bfloat16(x3 * scale);
}

// ------------------------------------------------------------------
// Kernel 2: fused tile GEMM (mma.sync bf16) + streamed softmax/label epilogue
// ------------------------------------------------------------------
__device__ __forceinline__ void load_stage(uint32_t sbuf, int row_a, int row_b,
                                           int kc, int tid) {
    const __nv_bfloat16* gA = g_x + (size_t)row_a * DIM + kc * TK;
    #pragma unroll
    for (int i = 0; i < 4; ++i) {                 // A: 128 rows x 8 chunks (16B)
        int id = tid + (i << 8);
        int r = id >> 3, c = id & 7;
        uint32_t sw = (uint32_t)(r * 128) + (uint32_t)((c ^ (r & 7)) << 4);
        cp_async16(sbuf + sw, gA + (size_t)r * DIM + c * 8);
    }
    const __nv_bfloat16* gB = g_x + (size_t)row_b * DIM + kc * TK;
    uint32_t bb = sbuf + A_BYTES;
    #pragma unroll
    for (int i = 0; i < 4; ++i) {                 // B: 128 rows x 8 chunks
        int id = tid + (i << 8);
        int r = id >> 3, c = id & 7;
        uint32_t sw = (uint32_t)(r * 128) + (uint32_t)((c ^ (r & 7)) << 4);
        cp_async16(bb + sw, gB + (size_t)r * DIM + c * 8);
    }
}

__global__ __launch_bounds__(THREADS, 2)
void coref_main_kernel(const float* __restrict__ labels) {
    extern __shared__ char smem_raw[];
    const uint32_t sb = smem_u32(smem_raw);

    const int tid  = threadIdx.x;
    const int lane = tid & 31;
    const int warp = tid >> 5;
    const int warp_m = warp & 1;        // 0..1 -> 64-row half
    const int warp_n = warp >> 1;       // 0..3 -> 32-col stripe

    const int tile_m = blockIdx.x >> 6;         // 0..63
    const int tile_n = blockIdx.x & 63;         // 0..63
    const int row0 = tile_m * TM;
    const int col0 = tile_n * TN;

    // Prologue: prefetch stages 0,1
    load_stage(sb,              row0, col0, 0, tid); CP_COMMIT();
    load_stage(sb + STG_BYTES,  row0, col0, 1, tid); CP_COMMIT();

    float acc[4][4][4];                          // [mi][ni][frag]
    #pragma unroll
    for (int mi = 0; mi < 4; ++mi)
        #pragma unroll
        for (int ni = 0; ni < 4; ++ni)
            #pragma unroll
            for (int j = 0; j < 4; ++j) acc[mi][ni][j] = 0.f;

    // Precompute swizzled ldmatrix addressing components
    // A fragment (16x16): lanes 0-7 -> (m0..7,k0-7), 8-15 -> (m8..15,k0-7),
    //                     16-23 -> (m0..7,k8-15), 24-31 -> (m8..15,k8-15)
    const int a_row_in = (lane & 7) + ((lane >> 3) & 1) * 8;   // 0..15 within 16-row tile
    const int a_hi     = lane >> 4;                            // k half chunk
    // B x4 (two 8-col n tiles): lanes 0-7 -> (n0..7,k0-7), 8-15 -> (n0..7,k8-15),
    //                           16-23 -> (n8..15,k0-7), 24-31 -> (n8..15,k8-15)
    const int b_row_in = (lane & 7) + (lane >> 4) * 8;         // 0..15 within 16-n group
    const int b_hi     = (lane >> 3) & 1;

    int a_rowbyte[4], a_rx[4];
    #pragma unroll
    for (int mi = 0; mi < 4; ++mi) {
        int r = warp_m * 64 + mi * 16 + a_row_in;
        a_rowbyte[mi] = r * 128;
        a_rx[mi] = r & 7;
    }
    int b_rowbyte[2], b_rx[2];
    #pragma unroll
    for (int g = 0; g < 2; ++g) {
        int r = warp_n * 32 + g * 16 + b_row_in;
        b_rowbyte[g] = r * 128;
        b_rx[g] = r & 7;
    }

    for (int kc = 0; kc < NKC; ++kc) {
        if (kc == NKC - 1) { CP_WAIT(0); } else { CP_WAIT(1); }
        __syncthreads();

        // Prefetch stage kc+2 (slot was consumed at iter kc-1)
        if (kc + 2 < NKC) {
            load_stage(sb + ((kc + 2) % STAGES) * STG_BYTES, row0, col0, kc + 2, tid);
            CP_COMMIT();
        }

        const uint32_t sA = sb + (kc % STAGES) * STG_BYTES;
        const uint32_t sB = sA + A_BYTES;

        #pragma unroll
        for (int kk = 0; kk < 4; ++kk) {
            const int kk2 = kk * 2;
            uint32_t Af[4][4], Bf[4][2];
            #pragma unroll
            for (int mi = 0; mi < 4; ++mi) {
                uint32_t addr = sA + a_rowbyte[mi]
                              + (uint32_t)(((kk2 + a_hi) ^ a_rx[mi]) << 4);
                LDSM_X4(Af[mi][0], Af[mi][1], Af[mi][2], Af[mi][3], addr);
            }
            #pragma unroll
            for (int g = 0; g < 2; ++g) {
                uint32_t q0, q1, q2, q3;
                uint32_t addr = sB + b_rowbyte[g]
                              + (uint32_t)(((kk2 + b_hi) ^ b_rx[g]) << 4);
                LDSM_X4(q0, q1, q2, q3, addr);
                Bf[g * 2 + 0][0] = q0; Bf[g * 2 + 0][1] = q1;
                Bf[g * 2 + 1][0] = q2; Bf[g * 2 + 1][1] = q3;
            }
            #pragma unroll
            for (int mi = 0; mi < 4; ++mi)
                #pragma unroll
                for (int ni = 0; ni < 4; ++ni)
                    mma_bf16(acc[mi][ni], Af[mi], Bf[ni]);
        }
    }

    // ---------------- epilogue ----------------
    // Accumulator fragment: rows t/4, t/4+8; cols 2*(t%4), +1
    const int qrow = lane >> 2;        // 0..7
    const int qcol = (lane & 3) * 2;   // 0,2,4,6
    const int stripe = tile_n * 4 + warp_n;           // global 32-col stripe id

    #pragma unroll
    for (int mi = 0; mi < 4; ++mi) {
        #pragma unroll
        for (int h = 0; h < 2; ++h) {
            const int grow = row0 + warp_m * 64 + mi * 16 + qrow + h * 8;
            const float* lrow = labels + (size_t)grow * N_ROWS + col0 + warp_n * 32;
            float s = 0.f, a = 0.f, b = 0.f;
            #pragma unroll
            for (int ni = 0; ni < 4; ++ni) {
                const int gcol = col0 + warp_n * 32 + ni * 8 + qcol;
                float2 lv = __ldcs((const float2*)(lrow + ni * 8 + qcol));
                float s0 = acc[mi][ni][h * 2 + 0];
                float s1 = acc[mi][ni][h * 2 + 1];
                if (gcol != grow) {
                    s += __expf(s0);
                    a = fmaf(lv.x, s0, a);
                    b += lv.x;
                }
                if (gcol + 1 != grow) {
                    s += __expf(s1);
                    a = fmaf(lv.y, s1, a);
                    b += lv.y;
                }
            }
            // quad reduce (lanes sharing qrow)
            s += __shfl_xor_sync(0xffffffffu, s, 1);
            s += __shfl_xor_sync(0xffffffffu, s, 2);
            a += __shfl_xor_sync(0xffffffffu, a, 1);
            a += __shfl_xor_sync(0xffffffffu, a, 2);
            b += __shfl_xor_sync(0xffffffffu, b, 1);
            b += __shfl_xor_sync(0xffffffffu, b, 2);
            if ((lane & 3) == 0) {
                g_ps[stripe * N_ROWS + grow] = s;
                g_pa[stripe * N_ROWS + grow] = a;
                g_pb[stripe * N_ROWS + grow] = b;
            }
        }
    }
}

// ------------------------------------------------------------------
// Kernel 3: per-row deterministic reduction of the 256 stripe partials
// ------------------------------------------------------------------
__global__ __launch_bounds__(128) void coref_rowloss_kernel() {
    const int row = blockIdx.x * 128 + threadIdx.x;
    float S = 0.f, A = 0.f, B = 0.f;
    #pragma unroll 8
    for (int t = 0; t < NSTRIPE; ++t) {
        S += g_ps[t * N_ROWS + row];
        A += g_pa[t * N_ROWS + row];
        B += g_pb[t * N_ROWS + row];
    }
    // loss_i = lse_i * B_i - A_i   (no max shift: |sim| <= 5)
    g_rowloss[row] = logf(S) * B - A;
}

// ------------------------------------------------------------------
// Kernel 4: deterministic fixed-tree scalar reduce (mean over rows)
// ------------------------------------------------------------------
__global__ __launch_bounds__(256) void coref_final_kernel(float* __restrict__ out) {
    __shared__ float sm[256];
    const int t = threadIdx.x;
    float v = 0.f;
    for (int i = t; i < N_ROWS; i += 256) v += g_rowloss[i];
    sm[t] = v;
    __syncthreads();
    #pragma unroll
    for (int s = 128; s > 0; s >>= 1) {
        if (t < s) sm[t] += sm[t + s];
        __syncthreads();
    }
    if (t == 0) out[0] = sm[0] * (1.0f / (float)N_ROWS);
}

// ------------------------------------------------------------------
// Launcher (graph-capturable)
// ------------------------------------------------------------------
extern "C" void kernel_launch(void* const* d_in, const int* in_sizes, int n_in,
                              void* d_out, int out_size) {
    const float* embs   = (const float*)d_in[0];
    const float* labels = (const float*)d_in[1];
    if (n_in >= 2 && in_sizes[0] == N_ROWS * N_ROWS) {  // defensive input-order check
        const float* tmp = embs; embs = labels; labels = tmp;
    }
    float* out = (float*)d_out;

    cudaFuncSetAttribute(coref_main_kernel,
                         cudaFuncAttributeMaxDynamicSharedMemorySize, SMEM_BYTES);

    coref_norm_kernel<<<N_ROWS, 256>>>(embs);
    coref_main_kernel<<<NTILE * NTILE, THREADS, SMEM_BYTES>>>(labels);
    coref_rowloss_kernel<<<N_ROWS / 128, 128>>>();
    coref_final_kernel<<<1, 256>>>(out);
}

// round 3
// speedup vs baseline: 1.5643x; 1.5643x over previous
#include <cuda_runtime.h>
#include <cuda_bf16.h>
#include <cstdint>

// ------------------------------------------------------------------
// Problem constants
// ------------------------------------------------------------------
constexpr int N_ROWS = 8192;
constexpr int DIM    = 1024;
constexpr float SQRT_INV_TEMP = 2.23606797749978969f;   // sqrt(1/0.2)

constexpr int TM = 128;               // CTA tile rows
constexpr int TN = 128;               // CTA tile cols
constexpr int TK = 64;                // bf16 K elems per stage (128 B rows)
constexpr int STAGES  = 3;
constexpr int THREADS = 256;          // 8 warps, 2 (M) x 4 (N)
constexpr int NKC = DIM / TK;         // 16 K chunks

constexpr int A_BYTES   = TM * TK * 2;            // 16 KB
constexpr int B_BYTES   = TN * TK * 2;            // 16 KB
constexpr int STG_BYTES = A_BYTES + B_BYTES;      // 32 KB
constexpr int SMEM_BYTES = STAGES * STG_BYTES;    // 96 KB

constexpr int NTILE   = N_ROWS / TM;              // 64
constexpr int NTRI    = NTILE * (NTILE + 1) / 2;  // 2080 upper-tri tiles
constexpr int NSTRIPE = N_ROWS / 32;              // 256 scratch slots per row

// ------------------------------------------------------------------
// Device scratch (static globals: allocation-free)
// ------------------------------------------------------------------
__device__ __nv_bfloat16 g_x[(size_t)N_ROWS * DIM];   // normalized * sqrt(5)
__device__ float g_ps[NSTRIPE * N_ROWS];              // partial sum exp(sim)
__device__ float g_pa[NSTRIPE * N_ROWS];              // partial sum lbl*sim
__device__ float g_pb[NSTRIPE * N_ROWS];              // partial sum lbl
__device__ float g_rowloss[N_ROWS];

// ------------------------------------------------------------------
// PTX helpers
// ------------------------------------------------------------------
__device__ __forceinline__ uint32_t smem_u32(const void* p) {
    uint32_t a;
    asm("{ .reg .u64 t; cvta.to.shared.u64 t, %1; cvt.u32.u64 %0, t; }" : "=r"(a) : "l"(p));
    return a;
}

__device__ __forceinline__ void cp_async16(uint32_t dst, const void* src) {
    asm volatile("{ .reg .u64 g; cvta.to.global.u64 g, %1; "
                 "cp.async.cg.shared.global [%0], [g], 16; }"
                 :: "r"(dst), "l"(src) : "memory");
}
#define CP_COMMIT() asm volatile("cp.async.commit_group;" ::: "memory")
#define CP_WAIT(N)  asm volatile("cp.async.wait_group %0;" :: "n"(N) : "memory")

#define LDSM_X4(R0, R1, R2, R3, ADDR) \
    asm volatile("ldmatrix.sync.aligned.m8n8.x4.shared.b16 {%0,%1,%2,%3}, [%4];" \
                 : "=r"(R0), "=r"(R1), "=r"(R2), "=r"(R3) : "r"(ADDR))

__device__ __forceinline__ void mma_bf16(float* d, const uint32_t* a, const uint32_t* b) {
    asm volatile(
        "mma.sync.aligned.m16n8k16.row.col.f32.bf16.bf16.f32 "
        "{%0,%1,%2,%3}, {%4,%5,%6,%7}, {%8,%9}, {%0,%1,%2,%3};"
        : "+f"(d[0]), "+f"(d[1]), "+f"(d[2]), "+f"(d[3])
        : "r"(a[0]), "r"(a[1]), "r"(a[2]), "r"(a[3]), "r"(b[0]), "r"(b[1]));
}

// ------------------------------------------------------------------
// Kernel 0: zero the scratch partial arrays (some slots never written
// under the triangular grid; kernel 3 sums all slots)
// ------------------------------------------------------------------
__global__ __launch_bounds__(256) void coref_zero_kernel() {
    const int i = blockIdx.x * 256 + threadIdx.x;   // grid covers exactly NSTRIPE*N_ROWS
    g_ps[i] = 0.f; g_pa[i] = 0.f; g_pb[i] = 0.f;
}

// ------------------------------------------------------------------
// Kernel 1: row-normalize, fold sqrt(1/T), cast to bf16
// ------------------------------------------------------------------
__global__ __launch_bounds__(256) void coref_norm_kernel(const float* __restrict__ e) {
    const int row = blockIdx.x, t = threadIdx.x;
    const float* r = e + (size_t)row * DIM;
    float x0 = r[t], x1 = r[t + 256], x2 = r[t + 512], x3 = r[t + 768];
    float ss = x0 * x0 + x1 * x1 + x2 * x2 + x3 * x3;
    #pragma unroll
    for (int o = 16; o > 0; o >>= 1) ss += __shfl_xor_sync(0xffffffffu, ss, o);
    __shared__ float ws[8];
    if ((t & 31) == 0) ws[t >> 5] = ss;
    __syncthreads();
    float tot = ws[0] + ws[1] + ws[2] + ws[3] + ws[4] + ws[5] + ws[6] + ws[7];
    float scale = SQRT_INV_TEMP / fmaxf(sqrtf(tot), 1e-8f);
    __nv_bfloat16* op = g_x + (size_t)row * DIM;
    op[t]       = __float2bfloat16(x0 * scale);
    op[t + 256] = __float2bfloat16(x1 * scale);
    op[t + 512] = __float2bfloat16(x2 * scale);
    op[t + 768] = __float2bfloat16(x3 * scale);
}

// ------------------------------------------------------------------
// Kernel 2: fused upper-triangular tile GEMM (mma.sync bf16)
//           + two-direction softmax/label epilogue (sim is symmetric)
// ------------------------------------------------------------------
__device__ __forceinline__ void load_stage(uint32_t sbuf, int row_a, int row_b,
                                           int kc, int tid) {
    const __nv_bfloat16* gA = g_x + (size_t)row_a * DIM + kc * TK;
    #pragma unroll
    for (int i = 0; i < 4; ++i) {                 // A: 128 rows x 8 chunks (16B)
        int id = tid + (i << 8);
        int r = id >> 3, c = id & 7;
        uint32_t sw = (uint32_t)(r * 128) + (uint32_t)((c ^ (r & 7)) << 4);
        cp_async16(sbuf + sw, gA + (size_t)r * DIM + c * 8);
    }
    const __nv_bfloat16* gB = g_x + (size_t)row_b * DIM + kc * TK;
    uint32_t bb = sbuf + A_BYTES;
    #pragma unroll
    for (int i = 0; i < 4; ++i) {                 // B: 128 rows x 8 chunks
        int id = tid + (i << 8);
        int r = id >> 3, c = id & 7;
        uint32_t sw = (uint32_t)(r * 128) + (uint32_t)((c ^ (r & 7)) << 4);
        cp_async16(bb + sw, gB + (size_t)r * DIM + c * 8);
    }
}

__global__ __launch_bounds__(THREADS, 2)
void coref_main_kernel(const float* __restrict__ labels) {
    extern __shared__ char smem_raw[];
    const uint32_t sb = smem_u32(smem_raw);

    const int tid  = threadIdx.x;
    const int lane = tid & 31;
    const int warp = tid >> 5;
    const int warp_m = warp & 1;        // 0..1 -> 64-row half
    const int warp_n = warp >> 1;       // 0..3 -> 32-col stripe

    // Decode blockIdx.x -> upper-triangular (tm, tn), tm <= tn
    int brem = blockIdx.x, tm = 0;
    while (brem >= NTILE - tm) { brem -= NTILE - tm; ++tm; }
    const int tn = tm + brem;
    const int row0 = tm * TM;
    const int col0 = tn * TN;
    const bool offdiag = (tm != tn);

    // Prologue: prefetch stages 0,1
    load_stage(sb,              row0, col0, 0, tid); CP_COMMIT();
    load_stage(sb + STG_BYTES,  row0, col0, 1, tid); CP_COMMIT();

    float acc[4][4][4];                          // [mi][ni][frag]
    #pragma unroll
    for (int mi = 0; mi < 4; ++mi)
        #pragma unroll
        for (int ni = 0; ni < 4; ++ni)
            #pragma unroll
            for (int j = 0; j < 4; ++j) acc[mi][ni][j] = 0.f;

    // ldmatrix lane addressing
    const int a_row_in = (lane & 7) + ((lane >> 3) & 1) * 8;
    const int a_hi     = lane >> 4;
    const int b_row_in = (lane & 7) + (lane >> 4) * 8;
    const int b_hi     = (lane >> 3) & 1;

    int a_rowbyte[4], a_rx[4];
    #pragma unroll
    for (int mi = 0; mi < 4; ++mi) {
        int r = warp_m * 64 + mi * 16 + a_row_in;
        a_rowbyte[mi] = r * 128;
        a_rx[mi] = r & 7;
    }
    int b_rowbyte[2], b_rx[2];
    #pragma unroll
    for (int g = 0; g < 2; ++g) {
        int r = warp_n * 32 + g * 16 + b_row_in;
        b_rowbyte[g] = r * 128;
        b_rx[g] = r & 7;
    }

    for (int kc = 0; kc < NKC; ++kc) {
        if (kc == NKC - 1) { CP_WAIT(0); } else { CP_WAIT(1); }
        __syncthreads();

        if (kc + 2 < NKC) {
            load_stage(sb + ((kc + 2) % STAGES) * STG_BYTES, row0, col0, kc + 2, tid);
            CP_COMMIT();
        }

        const uint32_t sA = sb + (kc % STAGES) * STG_BYTES;
        const uint32_t sB = sA + A_BYTES;

        #pragma unroll
        for (int kk = 0; kk < 4; ++kk) {
            const int kk2 = kk * 2;
            uint32_t Af[4][4], Bf[4][2];
            #pragma unroll
            for (int mi = 0; mi < 4; ++mi) {
                uint32_t addr = sA + a_rowbyte[mi]
                              + (uint32_t)(((kk2 + a_hi) ^ a_rx[mi]) << 4);
                LDSM_X4(Af[mi][0], Af[mi][1], Af[mi][2], Af[mi][3], addr);
            }
            #pragma unroll
            for (int g = 0; g < 2; ++g) {
                uint32_t q0, q1, q2, q3;
                uint32_t addr = sB + b_rowbyte[g]
                              + (uint32_t)(((kk2 + b_hi) ^ b_rx[g]) << 4);
                LDSM_X4(q0, q1, q2, q3, addr);
                Bf[g * 2 + 0][0] = q0; Bf[g * 2 + 0][1] = q1;
                Bf[g * 2 + 1][0] = q2; Bf[g * 2 + 1][1] = q3;
            }
            #pragma unroll
            for (int mi = 0; mi < 4; ++mi)
                #pragma unroll
                for (int ni = 0; ni < 4; ++ni)
                    mma_bf16(acc[mi][ni], Af[mi], Bf[ni]);
        }
    }

    // ---------------- epilogue ----------------
    // Fragment: rows qrow, qrow+8; cols 2*(lane%4), +1
    const int qrow = lane >> 2;        // 0..7
    const int qcol = (lane & 3) * 2;   // 0,2,4,6

    // ---- pass 1: row partials for m-block rows (dir-1) ----
    // slot = tn*4 + warp_n   (used for all tiles with this tn and tm <= tn)
    {
        const int stripe = tn * 4 + warp_n;
        #pragma unroll
        for (int mi = 0; mi < 4; ++mi) {
            #pragma unroll
            for (int h = 0; h < 2; ++h) {
                const int grow = row0 + warp_m * 64 + mi * 16 + qrow + h * 8;
                const float* lrow = labels + (size_t)grow * N_ROWS + col0 + warp_n * 32;
                float s = 0.f, a = 0.f, b = 0.f;
                #pragma unroll
                for (int ni = 0; ni < 4; ++ni) {
                    const int gcol = col0 + warp_n * 32 + ni * 8 + qcol;
                    float2 lv = __ldcs((const float2*)(lrow + ni * 8 + qcol));
                    float s0 = acc[mi][ni][h * 2 + 0];
                    float s1 = acc[mi][ni][h * 2 + 1];
                    if (gcol != grow) {                  // only binds on diag tiles
                        s += __expf(s0);
                        a = fmaf(lv.x, s0, a);
                        b += lv.x;
                    }
                    if (gcol + 1 != grow) {
                        s += __expf(s1);
                        a = fmaf(lv.y, s1, a);
                        b += lv.y;
                    }
                }
                s += __shfl_xor_sync(0xffffffffu, s, 1);
                s += __shfl_xor_sync(0xffffffffu, s, 2);
                a += __shfl_xor_sync(0xffffffffu, a, 1);
                a += __shfl_xor_sync(0xffffffffu, a, 2);
                b += __shfl_xor_sync(0xffffffffu, b, 1);
                b += __shfl_xor_sync(0xffffffffu, b, 2);
                if ((lane & 3) == 0) {
                    g_ps[stripe * N_ROWS + grow] = s;
                    g_pa[stripe * N_ROWS + grow] = a;
                    g_pb[stripe * N_ROWS + grow] = b;
                }
            }
        }
    }

    // ---- pass 2 (off-diag only): column partials for n-block rows (dir-2) ----
    // sim(i,j) == sim(j,i): column sums of this tile are row partials for the
    // n-block rows over the m-block columns. slot = tm*4 + warp_m*2
    // (disjoint from dir-1 slots since tm < tn here).
    if (offdiag) {
        const int slot = tm * 4 + warp_m * 2;
        #pragma unroll
        for (int ni = 0; ni < 4; ++ni) {
            const int gc0 = col0 + warp_n * 32 + ni * 8 + qcol;   // output rows gc0, gc0+1
            const float* lc0 = labels + (size_t)gc0 * N_ROWS;
            const float* lc1 = lc0 + N_ROWS;
            float s0 = 0.f, s1 = 0.f, a0 = 0.f, a1 = 0.f, b0 = 0.f, b1 = 0.f;
            #pragma unroll
            for (int mi = 0; mi < 4; ++mi) {
                #pragma unroll
                for (int h = 0; h < 2; ++h) {
                    const int grow = row0 + warp_m * 64 + mi * 16 + h * 8 + qrow;
                    float v0 = acc[mi][ni][h * 2 + 0];
                    float v1 = acc[mi][ni][h * 2 + 1];
                    float l0 = __ldcs(lc0 + grow);     // lbl[gc0][grow]
                    float l1 = __ldcs(lc1 + grow);     // lbl[gc0+1][grow]
                    s0 += __expf(v0);
                    s1 += __expf(v1);
                    a0 = fmaf(l0, v0, a0);
                    a1 = fmaf(l1, v1, a1);
                    b0 += l0;
                    b1 += l1;
                }
            }
            #pragma unroll
            for (int o = 4; o <= 16; o <<= 1) {
                s0 += __shfl_xor_sync(0xffffffffu, s0, o);
                s1 += __shfl_xor_sync(0xffffffffu, s1, o);
                a0 += __shfl_xor_sync(0xffffffffu, a0, o);
                a1 += __shfl_xor_sync(0xffffffffu, a1, o);
                b0 += __shfl_xor_sync(0xffffffffu, b0, o);
                b1 += __shfl_xor_sync(0xffffffffu, b1, o);
            }
            if (qrow == 0) {
                g_ps[slot * N_ROWS + gc0]     = s0;
                g_ps[slot * N_ROWS + gc0 + 1] = s1;
                g_pa[slot * N_ROWS + gc0]     = a0;
                g_pa[slot * N_ROWS + gc0 + 1] = a1;
                g_pb[slot * N_ROWS + gc0]     = b0;
                g_pb[slot * N_ROWS + gc0 + 1] = b1;
            }
        }
    }
}

// ------------------------------------------------------------------
// Kernel 3: per-row deterministic reduction of the stripe partials
// ------------------------------------------------------------------
__global__ __launch_bounds__(128) void coref_rowloss_kernel() {
    const int row = blockIdx.x * 128 + threadIdx.x;
    float S = 0.f, A = 0.f, B = 0.f;
    #pragma unroll 8
    for (int t = 0; t < NSTRIPE; ++t) {
        S += g_ps[t * N_ROWS + row];
        A += g_pa[t * N_ROWS + row];
        B += g_pb[t * N_ROWS + row];
    }
    // loss_i = lse_i * B_i - A_i   (no max shift: |sim| <= 5)
    g_rowloss[row] = logf(S) * B - A;
}

// ------------------------------------------------------------------
// Kernel 4: deterministic fixed-tree scalar reduce (mean over rows)
// ------------------------------------------------------------------
__global__ __launch_bounds__(256) void coref_final_kernel(float* __restrict__ out) {
    __shared__ float sm[256];
    const int t = threadIdx.x;
    float v = 0.f;
    for (int i = t; i < N_ROWS; i += 256) v += g_rowloss[i];
    sm[t] = v;
    __syncthreads();
    #pragma unroll
    for (int s = 128; s > 0; s >>= 1) {
        if (t < s) sm[t] += sm[t + s];
        __syncthreads();
    }
    if (t == 0) out[0] = sm[0] * (1.0f / (float)N_ROWS);
}

// ------------------------------------------------------------------
// Launcher (graph-capturable)
// ------------------------------------------------------------------
extern "C" void kernel_launch(void* const* d_in, const int* in_sizes, int n_in,
                              void* d_out, int out_size) {
    const float* embs   = (const float*)d_in[0];
    const float* labels = (const float*)d_in[1];
    if (n_in >= 2 && in_sizes[0] == N_ROWS * N_ROWS) {  // defensive input-order check
        const float* tmp = embs; embs = labels; labels = tmp;
    }
    float* out = (float*)d_out;

    cudaFuncSetAttribute(coref_main_kernel,
                         cudaFuncAttributeMaxDynamicSharedMemorySize, SMEM_BYTES);

    coref_zero_kernel<<<(NSTRIPE * N_ROWS) / 256, 256>>>();
    coref_norm_kernel<<<N_ROWS, 256>>>(embs);
    coref_main_kernel<<<NTRI, THREADS, SMEM_BYTES>>>(labels);
    coref_rowloss_kernel<<<N_ROWS / 128, 128>>>();
    coref_final_kernel<<<1, 256>>>(out);
}